// round 15
// baseline (speedup 1.0000x reference)
#include <cuda_runtime.h>
#include <cuda_bf16.h>
#include <math.h>

// ---------------- problem constants ----------------
#define D        128
#define NTYPES   6
#define NLAYERS  4
#define NRELS    10
#define E_LABEL  200000
#define NTOT     146000

// node types: 0=patient 1=visit 2=symptom 3=procedure 4=disease 5=drug
static const int kN[NTYPES]   = {20000, 100000, 4000, 8000, 10000, 4000};
static const int kOFF[NTYPES] = {0, 20000, 120000, 124000, 132000, 142000};

// relations (src,dst,E): order matches EI_NAMES
static const int kRS[NRELS] = {0,1,1,2,1,3,1,4,1,5};
static const int kRD[NRELS] = {1,0,2,1,3,1,4,1,5,1};
static const int kRE[NRELS] = {100000,100000,300000,300000,200000,200000,250000,250000,300000,300000};

// CSR storage offsets (host)
static const int kPtrOff[NRELS] = {0,100001,120002,124003,224004,232005,332006,342007,442008,446009};
static const int kSrcOff[NRELS] = {0,100000,200000,500000,800000,1000000,1200000,1450000,1700000,2000000};
static const size_t kMeanOff[NRELS] = {0ull,12800000ull,15360000ull,15872000ull,28672000ull,
                                       29696000ull,42496000ull,43776000ull,56576000ull,57088000ull};
// concat-weight row offset per dst type within a layer (layer stride = 2048 rows)
static const int kTypeRowOff[NTYPES] = {768, 0, 1024, 1280, 1536, 1792};

// ---------------- static device scratch ----------------
__device__ float g_x0[(size_t)NTOT * D];
__device__ float g_x1[(size_t)NTOT * D];
__device__ float g_mean[69888000ull];           // per-relation mean features
__device__ int   g_rowptr[546010];
__device__ int   g_srcs[2300000];
__device__ int   g_cnt[100000];
__device__ int   g_tmp[100000];
__device__ float g_bcat[(size_t)NLAYERS * 2048 * D];  // concatenated B per (layer,type)
__device__ float g_beff[(size_t)NLAYERS * NTYPES * D];
__device__ float g_part[256];

__device__ const int c_relcnt[NTYPES]     = {1, 5, 1, 1, 1, 1};
__device__ const int c_rels[NTYPES][5]    = {{1,0,0,0,0},{0,3,5,7,9},{2,0,0,0,0},
                                             {4,0,0,0,0},{6,0,0,0,0},{8,0,0,0,0}};
__device__ const int c_typeRowOff[NTYPES] = {768, 0, 1024, 1280, 1536, 1792};

// tf32 rounding (cvt.rna.tf32.f32), matching XLA:GPU default f32 matmul inputs.
__device__ __forceinline__ float tf32r(float x) {
    unsigned u;
    asm("cvt.rna.tf32.f32 %0, %1;" : "=r"(u) : "f"(x));
    return __uint_as_float(u);
}

// packed fp32x2 FMA (sm_103a; PTX-only, ptxas never emits FFMA2 from C++)
__device__ __forceinline__ void fma2(unsigned long long& d, unsigned long long a,
                                     unsigned long long b) {
    asm("fma.rn.f32x2 %0, %1, %2, %0;" : "+l"(d) : "l"(a), "l"(b));
}
__device__ __forceinline__ unsigned long long pk2(float lo, float hi) {
    unsigned long long r;
    asm("mov.b64 %0, {%1, %2};" : "=l"(r) : "f"(lo), "f"(hi));
    return r;
}
__device__ __forceinline__ float2 upk2(unsigned long long v) {
    float2 r;
    asm("mov.b64 {%0, %1}, %2;" : "=f"(r.x), "=f"(r.y) : "l"(v));
    return r;
}

// ---------------- CSR build ----------------
__global__ void kzero_int(int* __restrict__ p, int n) {
    int i = blockIdx.x * blockDim.x + threadIdx.x;
    if (i < n) p[i] = 0;
}

__global__ void hist_k(const int* __restrict__ ei, int E, int* __restrict__ cnt) {
    int e = blockIdx.x * blockDim.x + threadIdx.x;
    if (e < E) atomicAdd(&cnt[ei[E + e]], 1);
}

// single-block exclusive scan over up to 100000 bins -> rowptr & tmp
__global__ __launch_bounds__(1024) void scan_k(const int* __restrict__ cnt,
                                               int* __restrict__ rowptr,
                                               int* __restrict__ tmp, int N) {
    __shared__ int ssum[1024];
    int t = threadIdx.x;
    int chunk = (N + 1023) / 1024;
    int b0 = t * chunk, b1 = min(b0 + chunk, N);
    if (b0 > N) b0 = N;
    int s = 0;
    for (int i = b0; i < b1; i++) s += cnt[i];
    ssum[t] = s;
    __syncthreads();
    for (int o = 1; o < 1024; o <<= 1) {
        int v = (t >= o) ? ssum[t - o] : 0;
        __syncthreads();
        ssum[t] += v;
        __syncthreads();
    }
    int run = (t == 0) ? 0 : ssum[t - 1];
    for (int i = b0; i < b1; i++) {
        rowptr[i] = run;
        tmp[i] = run;
        run += cnt[i];
    }
    if (t == 1023) rowptr[N] = run;
}

__global__ void fill_k(const int* __restrict__ ei, int E, int* __restrict__ tmp,
                       int* __restrict__ srcs) {
    int e = blockIdx.x * blockDim.x + threadIdx.x;
    if (e < E) {
        int dst = ei[E + e];
        int pos = atomicAdd(&tmp[dst], 1);
        srcs[pos] = ei[e];
    }
}

// ---------------- gather-mean aggregation (no atomics, no zeroing) ----------------
__global__ void agg_mean(const float* __restrict__ x, const int* __restrict__ rowptr,
                         const int* __restrict__ srcs, float* __restrict__ mean, int Ndst)
{
    int v = (blockIdx.x * blockDim.x + threadIdx.x) >> 5;
    if (v >= Ndst) return;
    int lane = threadIdx.x & 31;
    int s = rowptr[v], e = rowptr[v + 1];
    float4 acc = make_float4(0.f, 0.f, 0.f, 0.f);
    int i = s;
    for (; i + 1 < e; i += 2) {
        int s0 = srcs[i], s1 = srcs[i + 1];
        float4 v0 = *(const float4*)&x[(size_t)s0 * D + (lane << 2)];
        float4 v1 = *(const float4*)&x[(size_t)s1 * D + (lane << 2)];
        acc.x += v0.x; acc.y += v0.y; acc.z += v0.z; acc.w += v0.w;
        acc.x += v1.x; acc.y += v1.y; acc.z += v1.z; acc.w += v1.w;
    }
    if (i < e) {
        int s0 = srcs[i];
        float4 v0 = *(const float4*)&x[(size_t)s0 * D + (lane << 2)];
        acc.x += v0.x; acc.y += v0.y; acc.z += v0.z; acc.w += v0.w;
    }
    float dmax = fmaxf((float)(e - s), 1.0f);
    float4 o;
    o.x = acc.x / dmax; o.y = acc.y / dmax; o.z = acc.z / dmax; o.w = acc.w / dmax;
    *(float4*)&mean[(size_t)v * D + (lane << 2)] = o;
}

// ---------------- effective weights: concat [sum tf32(Wr); tf32(Wl_r)...] ------
__global__ void compute_eff(const float* __restrict__ Wr, const float* __restrict__ Wl,
                            const float* __restrict__ bl,
                            float* __restrict__ bcat, float* __restrict__ beff) {
    int t = blockIdx.x, l = blockIdx.y;
    int cnt = c_relcnt[t];
    float* out = bcat + ((size_t)l * 2048 + c_typeRowOff[t]) * D;
    for (int idx = threadIdx.x; idx < D * D; idx += blockDim.x) {
        float s = 0.f;
        for (int j = 0; j < cnt; j++)
            s += tf32r(Wr[(size_t)(l * NRELS + c_rels[t][j]) * D * D + idx]);
        out[idx] = s;
    }
    for (int j = 0; j < cnt; j++) {
        const float* w = Wl + (size_t)(l * NRELS + c_rels[t][j]) * D * D;
        float* o = out + (size_t)(j + 1) * D * D;
        for (int idx = threadIdx.x; idx < D * D; idx += blockDim.x)
            o[idx] = tf32r(w[idx]);
    }
    for (int idx = threadIdx.x; idx < D; idx += blockDim.x) {
        float s = 0.f;
        for (int j = 0; j < cnt; j++)
            s += bl[(size_t)(l * NRELS + c_rels[t][j]) * D + idx];
        beff[(size_t)(l * NTYPES + t) * D + idx] = s;
    }
}

// ---------------- concatenated-K GEMM with FFMA2 ----------------
// C[M,128] = relu?( sum_kb tf32(A_kb[M,128]) @ B_kb[128,128] + bias )
struct GemmArgs { const float* a[6]; int nblk; };

__global__ __launch_bounds__(256) void gemm_cat(
    GemmArgs args, const float* __restrict__ B, const float* __restrict__ bias,
    float* __restrict__ C, int M, int dorelu)
{
    __shared__ float As[16][64];
    __shared__ float Bs[16][128];
    const int tid = threadIdx.x;
    const int m0  = blockIdx.x * 64;
    const int cg  = tid & 31;        // cols cg*4..+3
    const int rg  = tid >> 5;        // rows rg*8..+7 (4 pairs)
    const int lr  = tid >> 2;
    const int lk  = (tid & 3) << 2;
    const int grow = m0 + lr;
    const bool arow = (grow < M);

    unsigned long long acc[4][4];    // [row pair][col], lo=even row, hi=odd row
#pragma unroll
    for (int i = 0; i < 4; i++)
#pragma unroll
        for (int j = 0; j < 4; j++) acc[i][j] = 0ull;

    for (int kb = 0; kb < args.nblk; kb++) {
        const float* Ab = args.a[kb] + (size_t)grow * D;
        const float* Bb = B + (size_t)kb * D * D;
        for (int k0 = 0; k0 < D; k0 += 16) {
            float4 av = make_float4(0.f, 0.f, 0.f, 0.f);
            if (arow) av = *(const float4*)(Ab + k0 + lk);
            As[lk + 0][lr] = tf32r(av.x);
            As[lk + 1][lr] = tf32r(av.y);
            As[lk + 2][lr] = tf32r(av.z);
            As[lk + 3][lr] = tf32r(av.w);
#pragma unroll
            for (int t2 = 0; t2 < 2; t2++) {
                int idx = tid + t2 * 256;
                int bk = idx >> 5;
                int bn = (idx & 31) << 2;
                *(float4*)&Bs[bk][bn] = *(const float4*)&Bb[(size_t)(k0 + bk) * D + bn];
            }
            __syncthreads();
#pragma unroll
            for (int k = 0; k < 16; k++) {
                float4 b = *(float4*)&Bs[k][cg << 2];
                unsigned long long b0 = pk2(b.x, b.x);
                unsigned long long b1 = pk2(b.y, b.y);
                unsigned long long b2 = pk2(b.z, b.z);
                unsigned long long b3 = pk2(b.w, b.w);
#pragma unroll
                for (int i = 0; i < 4; i++) {
                    unsigned long long ap =
                        *(const unsigned long long*)&As[k][(rg << 3) + (i << 1)];
                    fma2(acc[i][0], ap, b0);
                    fma2(acc[i][1], ap, b1);
                    fma2(acc[i][2], ap, b2);
                    fma2(acc[i][3], ap, b3);
                }
            }
            __syncthreads();
        }
    }
    const int n0 = cg << 2;
    float4 bi = make_float4(0.f, 0.f, 0.f, 0.f);
    if (bias != nullptr) bi = *(const float4*)&bias[n0];
#pragma unroll
    for (int i = 0; i < 4; i++) {
        int r0 = m0 + (rg << 3) + (i << 1);
        float2 c0 = upk2(acc[i][0]);
        float2 c1 = upk2(acc[i][1]);
        float2 c2 = upk2(acc[i][2]);
        float2 c3 = upk2(acc[i][3]);
        float4 lo = make_float4(c0.x + bi.x, c1.x + bi.y, c2.x + bi.z, c3.x + bi.w);
        float4 hi = make_float4(c0.y + bi.x, c1.y + bi.y, c2.y + bi.z, c3.y + bi.w);
        if (dorelu) {
            lo.x = fmaxf(lo.x, 0.f); lo.y = fmaxf(lo.y, 0.f);
            lo.z = fmaxf(lo.z, 0.f); lo.w = fmaxf(lo.w, 0.f);
            hi.x = fmaxf(hi.x, 0.f); hi.y = fmaxf(hi.y, 0.f);
            hi.z = fmaxf(hi.z, 0.f); hi.w = fmaxf(hi.w, 0.f);
        }
        if (r0 < M)     *(float4*)&C[(size_t)r0 * D + n0] = lo;
        if (r0 + 1 < M) *(float4*)&C[(size_t)(r0 + 1) * D + n0] = hi;
    }
}

// ---------------- classifier (FFMA2 microkernel) ----------------
__global__ __launch_bounds__(256) void classifier_kernel(
    const float* __restrict__ xv, const float* __restrict__ xd,
    const int* __restrict__ eli,
    const float* __restrict__ W1, const float* __restrict__ b1,
    const float* __restrict__ w2, const float* __restrict__ b2,
    float* __restrict__ pred, int M)
{
    __shared__ float As[16][64];
    __shared__ float Bs[16][128];
    __shared__ int vidx[64];
    __shared__ int didx[64];
    const int tid = threadIdx.x;
    const int m0  = blockIdx.x * 64;
    if (tid < 64) {
        int r = m0 + tid;
        vidx[tid] = (r < M) ? eli[r] : 0;
    } else if (tid < 128) {
        int t = tid - 64, r = m0 + t;
        didx[t] = (r < M) ? eli[M + r] : 0;
    }
    __syncthreads();

    const int cg = tid & 31, rg = tid >> 5;
    const int lr = tid >> 2, lk = (tid & 3) << 2;
    const float* rowv = xv + (size_t)vidx[lr] * D;
    const float* rowd = xd + (size_t)didx[lr] * D;

    unsigned long long acc[4][4];
#pragma unroll
    for (int i = 0; i < 4; i++)
#pragma unroll
        for (int j = 0; j < 4; j++) acc[i][j] = 0ull;

    for (int k0 = 0; k0 < 2 * D; k0 += 16) {
        float4 av;
        if (k0 < D) av = *(const float4*)(rowv + k0 + lk);
        else        av = *(const float4*)(rowd + (k0 - D) + lk);
        As[lk + 0][lr] = tf32r(av.x);
        As[lk + 1][lr] = tf32r(av.y);
        As[lk + 2][lr] = tf32r(av.z);
        As[lk + 3][lr] = tf32r(av.w);
#pragma unroll
        for (int t2 = 0; t2 < 2; t2++) {
            int idx = tid + t2 * 256;
            int bk = idx >> 5;
            int bn = (idx & 31) << 2;
            float4 bv = *(const float4*)&W1[(size_t)(k0 + bk) * D + bn];
            bv.x = tf32r(bv.x); bv.y = tf32r(bv.y);
            bv.z = tf32r(bv.z); bv.w = tf32r(bv.w);
            *(float4*)&Bs[bk][bn] = bv;
        }
        __syncthreads();
#pragma unroll
        for (int k = 0; k < 16; k++) {
            float4 b = *(float4*)&Bs[k][cg << 2];
            unsigned long long b0 = pk2(b.x, b.x);
            unsigned long long b1p = pk2(b.y, b.y);
            unsigned long long b2p = pk2(b.z, b.z);
            unsigned long long b3p = pk2(b.w, b.w);
#pragma unroll
            for (int i = 0; i < 4; i++) {
                unsigned long long ap =
                    *(const unsigned long long*)&As[k][(rg << 3) + (i << 1)];
                fma2(acc[i][0], ap, b0);
                fma2(acc[i][1], ap, b1p);
                fma2(acc[i][2], ap, b2p);
                fma2(acc[i][3], ap, b3p);
            }
        }
        __syncthreads();
    }
    const int n0 = cg << 2;
    float4 bi = *(const float4*)&b1[n0];
    float4 w  = *(const float4*)&w2[n0];   // final gemv kept exact fp32
    float b2v = b2[0];
#pragma unroll
    for (int i = 0; i < 4; i++) {
        float2 c0 = upk2(acc[i][0]);
        float2 c1 = upk2(acc[i][1]);
        float2 c2 = upk2(acc[i][2]);
        float2 c3 = upk2(acc[i][3]);
        float plo = fmaxf(c0.x + bi.x, 0.f) * w.x + fmaxf(c1.x + bi.y, 0.f) * w.y +
                    fmaxf(c2.x + bi.z, 0.f) * w.z + fmaxf(c3.x + bi.w, 0.f) * w.w;
        float phi = fmaxf(c0.y + bi.x, 0.f) * w.x + fmaxf(c1.y + bi.y, 0.f) * w.y +
                    fmaxf(c2.y + bi.z, 0.f) * w.z + fmaxf(c3.y + bi.w, 0.f) * w.w;
#pragma unroll
        for (int off = 16; off; off >>= 1) {
            plo += __shfl_down_sync(0xffffffffu, plo, off);
            phi += __shfl_down_sync(0xffffffffu, phi, off);
        }
        if (cg == 0) {
            int r0 = m0 + (rg << 3) + (i << 1);
            if (r0 < M)     pred[r0] = plo + b2v;
            if (r0 + 1 < M) pred[r0 + 1] = phi + b2v;
        }
    }
}

// ---------------- loss ----------------
__global__ void loss_partial(const float* __restrict__ pred, const float* __restrict__ label,
                             float* __restrict__ part, int M)
{
    __shared__ float sh[256];
    float s = 0.f;
    for (int i = blockIdx.x * blockDim.x + threadIdx.x; i < M; i += gridDim.x * blockDim.x) {
        float z = pred[i];
        float sp = fmaxf(z, 0.f) + log1pf(expf(-fabsf(z)));
        s += sp - z * label[i];
    }
    sh[threadIdx.x] = s;
    __syncthreads();
    for (int o = 128; o; o >>= 1) {
        if (threadIdx.x < o) sh[threadIdx.x] += sh[threadIdx.x + o];
        __syncthreads();
    }
    if (threadIdx.x == 0) part[blockIdx.x] = sh[0];
}

__global__ void loss_final(const float* __restrict__ part, float* __restrict__ out)
{
    __shared__ float sh[256];
    sh[threadIdx.x] = part[threadIdx.x];
    __syncthreads();
    for (int o = 128; o; o >>= 1) {
        if (threadIdx.x < o) sh[threadIdx.x] += sh[threadIdx.x + o];
        __syncthreads();
    }
    if (threadIdx.x == 0) out[0] = sh[0] * (1.0f / (float)E_LABEL);
}

// ---------------- launcher ----------------
extern "C" void kernel_launch(void* const* d_in, const int* in_sizes, int n_in,
                              void* d_out, int out_size)
{
    (void)n_in; (void)out_size;
    const bool interleaved = (in_sizes[1] != 100000);
    const float* emb[NTYPES];
    for (int t = 0; t < NTYPES; t++)
        emb[t] = (const float*)d_in[interleaved ? (2 * t + 1) : (6 + t)];
    const int* ei[NRELS];
    for (int r = 0; r < NRELS; r++) ei[r] = (const int*)d_in[12 + r];
    const float* Wl  = (const float*)d_in[22];
    const float* bl  = (const float*)d_in[23];
    const float* Wr  = (const float*)d_in[24];
    const float* w1  = (const float*)d_in[25];
    const float* b1  = (const float*)d_in[26];
    const float* w2  = (const float*)d_in[27];
    const float* b2  = (const float*)d_in[28];
    const int*   eli  = (const int*)d_in[29];
    const float* elab = (const float*)d_in[30];

    float *x0, *x1, *mean, *bcat, *beff, *part;
    int *rowptr, *srcs, *cnt, *tmp;
    cudaGetSymbolAddress((void**)&x0,   g_x0);
    cudaGetSymbolAddress((void**)&x1,   g_x1);
    cudaGetSymbolAddress((void**)&mean, g_mean);
    cudaGetSymbolAddress((void**)&bcat, g_bcat);
    cudaGetSymbolAddress((void**)&beff, g_beff);
    cudaGetSymbolAddress((void**)&part, g_part);
    cudaGetSymbolAddress((void**)&rowptr, g_rowptr);
    cudaGetSymbolAddress((void**)&srcs,   g_srcs);
    cudaGetSymbolAddress((void**)&cnt,    g_cnt);
    cudaGetSymbolAddress((void**)&tmp,    g_tmp);

    // x0 = embeddings (node_id_* are arange -> gather is identity)
    for (int t = 0; t < NTYPES; t++)
        cudaMemcpyAsync(x0 + (size_t)kOFF[t] * D, emb[t],
                        (size_t)kN[t] * D * sizeof(float),
                        cudaMemcpyDeviceToDevice, 0);

    compute_eff<<<dim3(NTYPES, NLAYERS), 256>>>(Wr, Wl, bl, bcat, beff);

    // Build CSR per relation (edge lists are layer-invariant)
    for (int r = 0; r < NRELS; r++) {
        int Nd = kN[kRD[r]], E = kRE[r];
        kzero_int<<<(Nd + 255) / 256, 256>>>(cnt, Nd);
        hist_k<<<(E + 255) / 256, 256>>>(ei[r], E, cnt);
        scan_k<<<1, 1024>>>(cnt, rowptr + kPtrOff[r], tmp, Nd);
        fill_k<<<(E + 255) / 256, 256>>>(ei[r], E, tmp, srcs + kSrcOff[r]);
    }

    float* xb[2] = {x0, x1};
    for (int l = 0; l < NLAYERS; l++) {
        const float* xin = xb[l & 1];
        float* xout = xb[(l & 1) ^ 1];

        // gather-mean per relation (exact fp32 sum + div)
        for (int r = 0; r < NRELS; r++) {
            int Nd = kN[kRD[r]], st = kRS[r];
            agg_mean<<<(Nd * 32 + 255) / 256, 256>>>(
                xin + (size_t)kOFF[st] * D, rowptr + kPtrOff[r],
                srcs + kSrcOff[r], mean + kMeanOff[r], Nd);
        }

        // one concatenated GEMM per dst type (+ fused bias/relu)
        static const int tRels[NTYPES][5] = {{1,0,0,0,0},{0,3,5,7,9},{2,0,0,0,0},
                                             {4,0,0,0,0},{6,0,0,0,0},{8,0,0,0,0}};
        static const int tCnt[NTYPES] = {1,5,1,1,1,1};
        for (int t = 0; t < NTYPES; t++) {
            GemmArgs ga;
            ga.a[0] = xin + (size_t)kOFF[t] * D;
            for (int j = 0; j < tCnt[t]; j++)
                ga.a[1 + j] = mean + kMeanOff[tRels[t][j]];
            for (int j = tCnt[t] + 1; j < 6; j++) ga.a[j] = nullptr;
            ga.nblk = 1 + tCnt[t];
            gemm_cat<<<(kN[t] + 63) / 64, 256>>>(
                ga, bcat + ((size_t)l * 2048 + kTypeRowOff[t]) * D,
                beff + (size_t)(l * NTYPES + t) * D,
                xout + (size_t)kOFF[t] * D, kN[t], l < NLAYERS - 1 ? 1 : 0);
        }
    }

    float* outp = (float*)d_out;
    float* pred = outp + 1;
    classifier_kernel<<<(E_LABEL + 63) / 64, 256>>>(
        xb[0] + (size_t)kOFF[1] * D, xb[0] + (size_t)kOFF[5] * D,
        eli, w1, b1, w2, b2, pred, E_LABEL);
    loss_partial<<<256, 256>>>(pred, elab, part, E_LABEL);
    loss_final<<<1, 256>>>(part, outp);
}

// round 16
// speedup vs baseline: 1.2129x; 1.2129x over previous
#include <cuda_runtime.h>
#include <cuda_bf16.h>
#include <math.h>

// ---------------- problem constants ----------------
#define D        128
#define NTYPES   6
#define NLAYERS  4
#define NRELS    10
#define E_LABEL  200000
#define NTOT     146000
#define E_TOTAL  2300000
#define NBINS    546000

// node types: 0=patient 1=visit 2=symptom 3=procedure 4=disease 5=drug
static const int kN[NTYPES]   = {20000, 100000, 4000, 8000, 10000, 4000};
static const int kOFF[NTYPES] = {0, 20000, 120000, 124000, 132000, 142000};

// relations (src,dst,E): order matches EI_NAMES
static const int kRS[NRELS] = {0,1,1,2,1,3,1,4,1,5};
static const int kRD[NRELS] = {1,0,2,1,3,1,4,1,5,1};
static const int kRE[NRELS] = {100000,100000,300000,300000,200000,200000,250000,250000,300000,300000};

// concatenated-histogram bin offsets (cumulative Ndst per relation)
static const int kBinOff[NRELS] = {0,100000,120000,124000,224000,232000,332000,342000,442000,446000};
static const size_t kMeanOff[NRELS] = {0ull,12800000ull,15360000ull,15872000ull,28672000ull,
                                       29696000ull,42496000ull,43776000ull,56576000ull,57088000ull};
// concat-weight row offset per dst type within a layer (layer stride = 2048 rows)
static const int kTypeRowOff[NTYPES] = {768, 0, 1024, 1280, 1536, 1792};

// ---------------- static device scratch ----------------
__device__ float g_x0[(size_t)NTOT * D];
__device__ float g_x1[(size_t)NTOT * D];
__device__ float g_mean[69888000ull];           // per-relation mean features
__device__ int   g_pref[NBINS + 1];             // global exclusive scan (== rowptrs)
__device__ int   g_srcs[E_TOTAL];
__device__ int   g_cnt[NBINS];
__device__ int   g_tmpp[NBINS];
__device__ int   g_spart[256];
__device__ float g_bcat[(size_t)NLAYERS * 2048 * D];  // concatenated B per (layer,type)
__device__ float g_beff[(size_t)NLAYERS * NTYPES * D];
__device__ float g_part[256];

__device__ const int c_relcnt[NTYPES]     = {1, 5, 1, 1, 1, 1};
__device__ const int c_rels[NTYPES][5]    = {{1,0,0,0,0},{0,3,5,7,9},{2,0,0,0,0},
                                             {4,0,0,0,0},{6,0,0,0,0},{8,0,0,0,0}};
__device__ const int c_typeRowOff[NTYPES] = {768, 0, 1024, 1280, 1536, 1792};
__device__ const int c_E[NRELS]      = {100000,100000,300000,300000,200000,200000,250000,250000,300000,300000};
__device__ const int c_binoff[NRELS] = {0,100000,120000,124000,224000,232000,332000,342000,442000,446000};

// tf32 rounding (cvt.rna.tf32.f32), matching XLA:GPU default f32 matmul inputs.
__device__ __forceinline__ float tf32r(float x) {
    unsigned u;
    asm("cvt.rna.tf32.f32 %0, %1;" : "=r"(u) : "f"(x));
    return __uint_as_float(u);
}

// packed fp32x2 FMA (sm_103a; PTX-only, ptxas never emits FFMA2 from C++)
__device__ __forceinline__ void fma2(unsigned long long& d, unsigned long long a,
                                     unsigned long long b) {
    asm("fma.rn.f32x2 %0, %1, %2, %0;" : "+l"(d) : "l"(a), "l"(b));
}
__device__ __forceinline__ unsigned long long pk2(float lo, float hi) {
    unsigned long long r;
    asm("mov.b64 %0, {%1, %2};" : "=l"(r) : "f"(lo), "f"(hi));
    return r;
}
__device__ __forceinline__ float2 upk2(unsigned long long v) {
    float2 r;
    asm("mov.b64 {%0, %1}, %2;" : "=f"(r.x), "=f"(r.y) : "l"(v));
    return r;
}

// ---------------- CSR build: concatenated hist + chip-wide scan ----------------
struct EiArgs { const int* ei[NRELS]; };

__global__ void kzero_int(int* __restrict__ p, int n) {
    int i = blockIdx.x * blockDim.x + threadIdx.x;
    if (i < n) p[i] = 0;
}

__global__ void hist_all(EiArgs ea, int* __restrict__ cnt) {
    int r = blockIdx.y;
    int E = c_E[r];
    int e = blockIdx.x * blockDim.x + threadIdx.x;
    if (e < E) atomicAdd(&cnt[c_binoff[r] + ea.ei[r][E + e]], 1);
}

#define SCAN_TPB 1024
#define SCAN_IPT 4
#define SCAN_IPB 4096
#define SCAN_NBLK 134   // ceil(546000/4096)

__global__ __launch_bounds__(SCAN_TPB) void scan_part(const int* __restrict__ cnt,
                                                      int* __restrict__ part) {
    __shared__ int sh[SCAN_TPB];
    int base = blockIdx.x * SCAN_IPB + threadIdx.x * SCAN_IPT;
    int s = 0;
#pragma unroll
    for (int i = 0; i < SCAN_IPT; i++) {
        int idx = base + i;
        if (idx < NBINS) s += cnt[idx];
    }
    sh[threadIdx.x] = s;
    __syncthreads();
    for (int o = SCAN_TPB / 2; o; o >>= 1) {
        if (threadIdx.x < o) sh[threadIdx.x] += sh[threadIdx.x + o];
        __syncthreads();
    }
    if (threadIdx.x == 0) part[blockIdx.x] = sh[0];
}

__global__ void scan_top(int* __restrict__ part, int* __restrict__ pref) {
    __shared__ int sh[256];
    int t = threadIdx.x;
    int v = (t < SCAN_NBLK) ? part[t] : 0;
    sh[t] = v;
    __syncthreads();
    for (int o = 1; o < 256; o <<= 1) {
        int x = (t >= o) ? sh[t - o] : 0;
        __syncthreads();
        sh[t] += x;
        __syncthreads();
    }
    if (t < SCAN_NBLK) part[t] = t ? sh[t - 1] : 0;
    if (t == 255) pref[NBINS] = sh[255];   // grand total (== E_TOTAL)
}

__global__ __launch_bounds__(SCAN_TPB) void scan_final(
    const int* __restrict__ cnt, const int* __restrict__ part,
    int* __restrict__ pref, int* __restrict__ tmp) {
    __shared__ int sh[SCAN_TPB];
    int t = threadIdx.x;
    int base = blockIdx.x * SCAN_IPB + t * SCAN_IPT;
    int v[SCAN_IPT];
    int s = 0;
#pragma unroll
    for (int i = 0; i < SCAN_IPT; i++) {
        int idx = base + i;
        v[i] = (idx < NBINS) ? cnt[idx] : 0;
        s += v[i];
    }
    sh[t] = s;
    __syncthreads();
    for (int o = 1; o < SCAN_TPB; o <<= 1) {
        int x = (t >= o) ? sh[t - o] : 0;
        __syncthreads();
        sh[t] += x;
        __syncthreads();
    }
    int run = part[blockIdx.x] + (t ? sh[t - 1] : 0);
#pragma unroll
    for (int i = 0; i < SCAN_IPT; i++) {
        int idx = base + i;
        if (idx < NBINS) {
            pref[idx] = run;
            tmp[idx] = run;
            run += v[i];
        }
    }
}

__global__ void fill_all(EiArgs ea, int* __restrict__ tmp, int* __restrict__ srcs) {
    int r = blockIdx.y;
    int E = c_E[r];
    int e = blockIdx.x * blockDim.x + threadIdx.x;
    if (e < E) {
        int dst = ea.ei[r][E + e];
        int pos = atomicAdd(&tmp[c_binoff[r] + dst], 1);
        srcs[pos] = ea.ei[r][e];
    }
}

// ---------------- gather-mean aggregation (no atomics, no zeroing) ----------------
__global__ void agg_mean(const float* __restrict__ x, const int* __restrict__ rowptr,
                         const int* __restrict__ srcs, float* __restrict__ mean, int Ndst)
{
    int v = (blockIdx.x * blockDim.x + threadIdx.x) >> 5;
    if (v >= Ndst) return;
    int lane = threadIdx.x & 31;
    int s = rowptr[v], e = rowptr[v + 1];
    float4 acc = make_float4(0.f, 0.f, 0.f, 0.f);
    int i = s;
    for (; i + 1 < e; i += 2) {
        int s0 = srcs[i], s1 = srcs[i + 1];
        float4 v0 = *(const float4*)&x[(size_t)s0 * D + (lane << 2)];
        float4 v1 = *(const float4*)&x[(size_t)s1 * D + (lane << 2)];
        acc.x += v0.x; acc.y += v0.y; acc.z += v0.z; acc.w += v0.w;
        acc.x += v1.x; acc.y += v1.y; acc.z += v1.z; acc.w += v1.w;
    }
    if (i < e) {
        int s0 = srcs[i];
        float4 v0 = *(const float4*)&x[(size_t)s0 * D + (lane << 2)];
        acc.x += v0.x; acc.y += v0.y; acc.z += v0.z; acc.w += v0.w;
    }
    float dmax = fmaxf((float)(e - s), 1.0f);
    float4 o;
    o.x = acc.x / dmax; o.y = acc.y / dmax; o.z = acc.z / dmax; o.w = acc.w / dmax;
    *(float4*)&mean[(size_t)v * D + (lane << 2)] = o;
}

// ---------------- effective weights: concat [sum tf32(Wr); tf32(Wl_r)...] ------
__global__ void compute_eff(const float* __restrict__ Wr, const float* __restrict__ Wl,
                            const float* __restrict__ bl,
                            float* __restrict__ bcat, float* __restrict__ beff) {
    int t = blockIdx.x, l = blockIdx.y;
    int cnt = c_relcnt[t];
    float* out = bcat + ((size_t)l * 2048 + c_typeRowOff[t]) * D;
    for (int idx = threadIdx.x; idx < D * D; idx += blockDim.x) {
        float s = 0.f;
        for (int j = 0; j < cnt; j++)
            s += tf32r(Wr[(size_t)(l * NRELS + c_rels[t][j]) * D * D + idx]);
        out[idx] = s;
    }
    for (int j = 0; j < cnt; j++) {
        const float* w = Wl + (size_t)(l * NRELS + c_rels[t][j]) * D * D;
        float* o = out + (size_t)(j + 1) * D * D;
        for (int idx = threadIdx.x; idx < D * D; idx += blockDim.x)
            o[idx] = tf32r(w[idx]);
    }
    for (int idx = threadIdx.x; idx < D; idx += blockDim.x) {
        float s = 0.f;
        for (int j = 0; j < cnt; j++)
            s += bl[(size_t)(l * NRELS + c_rels[t][j]) * D + idx];
        beff[(size_t)(l * NTYPES + t) * D + idx] = s;
    }
}

// ---------------- concatenated-K GEMM with FFMA2 ----------------
// C[M,128] = relu?( sum_kb tf32(A_kb[M,128]) @ B_kb[128,128] + bias )
struct GemmArgs { const float* a[6]; int nblk; };

__global__ __launch_bounds__(256) void gemm_cat(
    GemmArgs args, const float* __restrict__ B, const float* __restrict__ bias,
    float* __restrict__ C, int M, int dorelu)
{
    __shared__ float As[16][64];
    __shared__ float Bs[16][128];
    const int tid = threadIdx.x;
    const int m0  = blockIdx.x * 64;
    const int cg  = tid & 31;        // cols cg*4..+3
    const int rg  = tid >> 5;        // rows rg*8..+7 (4 pairs)
    const int lr  = tid >> 2;
    const int lk  = (tid & 3) << 2;
    const int grow = m0 + lr;
    const bool arow = (grow < M);

    unsigned long long acc[4][4];    // [row pair][col], lo=even row, hi=odd row
#pragma unroll
    for (int i = 0; i < 4; i++)
#pragma unroll
        for (int j = 0; j < 4; j++) acc[i][j] = 0ull;

    for (int kb = 0; kb < args.nblk; kb++) {
        const float* Ab = args.a[kb] + (size_t)grow * D;
        const float* Bb = B + (size_t)kb * D * D;
        for (int k0 = 0; k0 < D; k0 += 16) {
            float4 av = make_float4(0.f, 0.f, 0.f, 0.f);
            if (arow) av = *(const float4*)(Ab + k0 + lk);
            As[lk + 0][lr] = tf32r(av.x);
            As[lk + 1][lr] = tf32r(av.y);
            As[lk + 2][lr] = tf32r(av.z);
            As[lk + 3][lr] = tf32r(av.w);
#pragma unroll
            for (int t2 = 0; t2 < 2; t2++) {
                int idx = tid + t2 * 256;
                int bk = idx >> 5;
                int bn = (idx & 31) << 2;
                *(float4*)&Bs[bk][bn] = *(const float4*)&Bb[(size_t)(k0 + bk) * D + bn];
            }
            __syncthreads();
#pragma unroll
            for (int k = 0; k < 16; k++) {
                float4 b = *(float4*)&Bs[k][cg << 2];
                unsigned long long b0 = pk2(b.x, b.x);
                unsigned long long b1 = pk2(b.y, b.y);
                unsigned long long b2 = pk2(b.z, b.z);
                unsigned long long b3 = pk2(b.w, b.w);
#pragma unroll
                for (int i = 0; i < 4; i++) {
                    unsigned long long ap =
                        *(const unsigned long long*)&As[k][(rg << 3) + (i << 1)];
                    fma2(acc[i][0], ap, b0);
                    fma2(acc[i][1], ap, b1);
                    fma2(acc[i][2], ap, b2);
                    fma2(acc[i][3], ap, b3);
                }
            }
            __syncthreads();
        }
    }
    const int n0 = cg << 2;
    float4 bi = make_float4(0.f, 0.f, 0.f, 0.f);
    if (bias != nullptr) bi = *(const float4*)&bias[n0];
#pragma unroll
    for (int i = 0; i < 4; i++) {
        int r0 = m0 + (rg << 3) + (i << 1);
        float2 c0 = upk2(acc[i][0]);
        float2 c1 = upk2(acc[i][1]);
        float2 c2 = upk2(acc[i][2]);
        float2 c3 = upk2(acc[i][3]);
        float4 lo = make_float4(c0.x + bi.x, c1.x + bi.y, c2.x + bi.z, c3.x + bi.w);
        float4 hi = make_float4(c0.y + bi.x, c1.y + bi.y, c2.y + bi.z, c3.y + bi.w);
        if (dorelu) {
            lo.x = fmaxf(lo.x, 0.f); lo.y = fmaxf(lo.y, 0.f);
            lo.z = fmaxf(lo.z, 0.f); lo.w = fmaxf(lo.w, 0.f);
            hi.x = fmaxf(hi.x, 0.f); hi.y = fmaxf(hi.y, 0.f);
            hi.z = fmaxf(hi.z, 0.f); hi.w = fmaxf(hi.w, 0.f);
        }
        if (r0 < M)     *(float4*)&C[(size_t)r0 * D + n0] = lo;
        if (r0 + 1 < M) *(float4*)&C[(size_t)(r0 + 1) * D + n0] = hi;
    }
}

// ---------------- classifier (FFMA2 microkernel) ----------------
__global__ __launch_bounds__(256) void classifier_kernel(
    const float* __restrict__ xv, const float* __restrict__ xd,
    const int* __restrict__ eli,
    const float* __restrict__ W1, const float* __restrict__ b1,
    const float* __restrict__ w2, const float* __restrict__ b2,
    float* __restrict__ pred, int M)
{
    __shared__ float As[16][64];
    __shared__ float Bs[16][128];
    __shared__ int vidx[64];
    __shared__ int didx[64];
    const int tid = threadIdx.x;
    const int m0  = blockIdx.x * 64;
    if (tid < 64) {
        int r = m0 + tid;
        vidx[tid] = (r < M) ? eli[r] : 0;
    } else if (tid < 128) {
        int t = tid - 64, r = m0 + t;
        didx[t] = (r < M) ? eli[M + r] : 0;
    }
    __syncthreads();

    const int cg = tid & 31, rg = tid >> 5;
    const int lr = tid >> 2, lk = (tid & 3) << 2;
    const float* rowv = xv + (size_t)vidx[lr] * D;
    const float* rowd = xd + (size_t)didx[lr] * D;

    unsigned long long acc[4][4];
#pragma unroll
    for (int i = 0; i < 4; i++)
#pragma unroll
        for (int j = 0; j < 4; j++) acc[i][j] = 0ull;

    for (int k0 = 0; k0 < 2 * D; k0 += 16) {
        float4 av;
        if (k0 < D) av = *(const float4*)(rowv + k0 + lk);
        else        av = *(const float4*)(rowd + (k0 - D) + lk);
        As[lk + 0][lr] = tf32r(av.x);
        As[lk + 1][lr] = tf32r(av.y);
        As[lk + 2][lr] = tf32r(av.z);
        As[lk + 3][lr] = tf32r(av.w);
#pragma unroll
        for (int t2 = 0; t2 < 2; t2++) {
            int idx = tid + t2 * 256;
            int bk = idx >> 5;
            int bn = (idx & 31) << 2;
            float4 bv = *(const float4*)&W1[(size_t)(k0 + bk) * D + bn];
            bv.x = tf32r(bv.x); bv.y = tf32r(bv.y);
            bv.z = tf32r(bv.z); bv.w = tf32r(bv.w);
            *(float4*)&Bs[bk][bn] = bv;
        }
        __syncthreads();
#pragma unroll
        for (int k = 0; k < 16; k++) {
            float4 b = *(float4*)&Bs[k][cg << 2];
            unsigned long long b0 = pk2(b.x, b.x);
            unsigned long long b1p = pk2(b.y, b.y);
            unsigned long long b2p = pk2(b.z, b.z);
            unsigned long long b3p = pk2(b.w, b.w);
#pragma unroll
            for (int i = 0; i < 4; i++) {
                unsigned long long ap =
                    *(const unsigned long long*)&As[k][(rg << 3) + (i << 1)];
                fma2(acc[i][0], ap, b0);
                fma2(acc[i][1], ap, b1p);
                fma2(acc[i][2], ap, b2p);
                fma2(acc[i][3], ap, b3p);
            }
        }
        __syncthreads();
    }
    const int n0 = cg << 2;
    float4 bi = *(const float4*)&b1[n0];
    float4 w  = *(const float4*)&w2[n0];   // final gemv kept exact fp32
    float b2v = b2[0];
#pragma unroll
    for (int i = 0; i < 4; i++) {
        float2 c0 = upk2(acc[i][0]);
        float2 c1 = upk2(acc[i][1]);
        float2 c2 = upk2(acc[i][2]);
        float2 c3 = upk2(acc[i][3]);
        float plo = fmaxf(c0.x + bi.x, 0.f) * w.x + fmaxf(c1.x + bi.y, 0.f) * w.y +
                    fmaxf(c2.x + bi.z, 0.f) * w.z + fmaxf(c3.x + bi.w, 0.f) * w.w;
        float phi = fmaxf(c0.y + bi.x, 0.f) * w.x + fmaxf(c1.y + bi.y, 0.f) * w.y +
                    fmaxf(c2.y + bi.z, 0.f) * w.z + fmaxf(c3.y + bi.w, 0.f) * w.w;
#pragma unroll
        for (int off = 16; off; off >>= 1) {
            plo += __shfl_down_sync(0xffffffffu, plo, off);
            phi += __shfl_down_sync(0xffffffffu, phi, off);
        }
        if (cg == 0) {
            int r0 = m0 + (rg << 3) + (i << 1);
            if (r0 < M)     pred[r0] = plo + b2v;
            if (r0 + 1 < M) pred[r0 + 1] = phi + b2v;
        }
    }
}

// ---------------- loss ----------------
__global__ void loss_partial(const float* __restrict__ pred, const float* __restrict__ label,
                             float* __restrict__ part, int M)
{
    __shared__ float sh[256];
    float s = 0.f;
    for (int i = blockIdx.x * blockDim.x + threadIdx.x; i < M; i += gridDim.x * blockDim.x) {
        float z = pred[i];
        float sp = fmaxf(z, 0.f) + log1pf(expf(-fabsf(z)));
        s += sp - z * label[i];
    }
    sh[threadIdx.x] = s;
    __syncthreads();
    for (int o = 128; o; o >>= 1) {
        if (threadIdx.x < o) sh[threadIdx.x] += sh[threadIdx.x + o];
        __syncthreads();
    }
    if (threadIdx.x == 0) part[blockIdx.x] = sh[0];
}

__global__ void loss_final(const float* __restrict__ part, float* __restrict__ out)
{
    __shared__ float sh[256];
    sh[threadIdx.x] = part[threadIdx.x];
    __syncthreads();
    for (int o = 128; o; o >>= 1) {
        if (threadIdx.x < o) sh[threadIdx.x] += sh[threadIdx.x + o];
        __syncthreads();
    }
    if (threadIdx.x == 0) out[0] = sh[0] * (1.0f / (float)E_LABEL);
}

// ---------------- launcher ----------------
extern "C" void kernel_launch(void* const* d_in, const int* in_sizes, int n_in,
                              void* d_out, int out_size)
{
    (void)n_in; (void)out_size;
    const bool interleaved = (in_sizes[1] != 100000);
    const float* emb[NTYPES];
    for (int t = 0; t < NTYPES; t++)
        emb[t] = (const float*)d_in[interleaved ? (2 * t + 1) : (6 + t)];
    EiArgs ea;
    for (int r = 0; r < NRELS; r++) ea.ei[r] = (const int*)d_in[12 + r];
    const float* Wl  = (const float*)d_in[22];
    const float* bl  = (const float*)d_in[23];
    const float* Wr  = (const float*)d_in[24];
    const float* w1  = (const float*)d_in[25];
    const float* b1  = (const float*)d_in[26];
    const float* w2  = (const float*)d_in[27];
    const float* b2  = (const float*)d_in[28];
    const int*   eli  = (const int*)d_in[29];
    const float* elab = (const float*)d_in[30];

    float *x0, *x1, *mean, *bcat, *beff, *part;
    int *pref, *srcs, *cnt, *tmpp, *spart;
    cudaGetSymbolAddress((void**)&x0,   g_x0);
    cudaGetSymbolAddress((void**)&x1,   g_x1);
    cudaGetSymbolAddress((void**)&mean, g_mean);
    cudaGetSymbolAddress((void**)&bcat, g_bcat);
    cudaGetSymbolAddress((void**)&beff, g_beff);
    cudaGetSymbolAddress((void**)&part, g_part);
    cudaGetSymbolAddress((void**)&pref, g_pref);
    cudaGetSymbolAddress((void**)&srcs, g_srcs);
    cudaGetSymbolAddress((void**)&cnt,  g_cnt);
    cudaGetSymbolAddress((void**)&tmpp, g_tmpp);
    cudaGetSymbolAddress((void**)&spart, g_spart);

    // x0 = embeddings (node_id_* are arange -> gather is identity)
    for (int t = 0; t < NTYPES; t++)
        cudaMemcpyAsync(x0 + (size_t)kOFF[t] * D, emb[t],
                        (size_t)kN[t] * D * sizeof(float),
                        cudaMemcpyDeviceToDevice, 0);

    compute_eff<<<dim3(NTYPES, NLAYERS), 256>>>(Wr, Wl, bl, bcat, beff);

    // ---- CSR build: concatenated histogram, ONE chip-wide scan, fill ----
    {
        const int maxE = 300000;
        kzero_int<<<(NBINS + 255) / 256, 256>>>(cnt, NBINS);
        hist_all<<<dim3((maxE + 255) / 256, NRELS), 256>>>(ea, cnt);
        scan_part<<<SCAN_NBLK, SCAN_TPB>>>(cnt, spart);
        scan_top<<<1, 256>>>(spart, pref);
        scan_final<<<SCAN_NBLK, SCAN_TPB>>>(cnt, spart, pref, tmpp);
        fill_all<<<dim3((maxE + 255) / 256, NRELS), 256>>>(ea, tmpp, srcs);
    }

    float* xb[2] = {x0, x1};
    for (int l = 0; l < NLAYERS; l++) {
        const float* xin = xb[l & 1];
        float* xout = xb[(l & 1) ^ 1];

        // gather-mean per relation (exact fp32 sum + div); rowptr = global pref
        for (int r = 0; r < NRELS; r++) {
            int Nd = kN[kRD[r]], st = kRS[r];
            agg_mean<<<(Nd * 32 + 255) / 256, 256>>>(
                xin + (size_t)kOFF[st] * D, pref + kBinOff[r],
                srcs, mean + kMeanOff[r], Nd);
        }

        // one concatenated GEMM per dst type (+ fused bias/relu)
        static const int tRels[NTYPES][5] = {{1,0,0,0,0},{0,3,5,7,9},{2,0,0,0,0},
                                             {4,0,0,0,0},{6,0,0,0,0},{8,0,0,0,0}};
        static const int tCnt[NTYPES] = {1,5,1,1,1,1};
        for (int t = 0; t < NTYPES; t++) {
            GemmArgs ga;
            ga.a[0] = xin + (size_t)kOFF[t] * D;
            for (int j = 0; j < tCnt[t]; j++)
                ga.a[1 + j] = mean + kMeanOff[tRels[t][j]];
            for (int j = tCnt[t] + 1; j < 6; j++) ga.a[j] = nullptr;
            ga.nblk = 1 + tCnt[t];
            gemm_cat<<<(kN[t] + 63) / 64, 256>>>(
                ga, bcat + ((size_t)l * 2048 + kTypeRowOff[t]) * D,
                beff + (size_t)(l * NTYPES + t) * D,
                xout + (size_t)kOFF[t] * D, kN[t], l < NLAYERS - 1 ? 1 : 0);
        }
    }

    float* outp = (float*)d_out;
    float* pred = outp + 1;
    classifier_kernel<<<(E_LABEL + 63) / 64, 256>>>(
        xb[0] + (size_t)kOFF[1] * D, xb[0] + (size_t)kOFF[5] * D,
        eli, w1, b1, w2, b2, pred, E_LABEL);
    loss_partial<<<256, 256>>>(pred, elab, part, E_LABEL);
    loss_final<<<1, 256>>>(part, outp);
}